// round 16
// baseline (speedup 1.0000x reference)
#include <cuda_runtime.h>
#include <math.h>

#define NN 4096
#define GC 256              // LUT cells over [-8, 8), width 1/16
#define FULLM 0xffffffffu

// global scratch (static — no allocs)
__device__ float2   g_cd[NN * GC];   // per-row per-cell (c, d)
__device__ unsigned g_off[NN];       // per-j LUT byte offset (idx << 4)

// ---------------- build: TWO rows per warp; emits g_cd directly ----------------
__global__ void __launch_bounds__(256) build_pwl2(
    const float* __restrict__ x,
    const float* __restrict__ WA0, const float* __restrict__ bA0,
    const float* __restrict__ WA1, const float* __restrict__ bA1,
    const float* __restrict__ WA2, const float* __restrict__ bA2,
    const float* __restrict__ wA)
{
    __shared__ float  sT[8][2][16];
    __shared__ int    sK[8][2][16];
    __shared__ float  sB[8][2][66];      // segment left bounds, padded
    __shared__ float2 sCD[8][2][64];     // segment (c, d)
    const int warp = threadIdx.x >> 5, lane = threadIdx.x & 31;
    const int half = lane >> 4;
    const int hl   = lane & 15;
    const int i = blockIdx.x * 16 + warp * 2 + half;

    // folded offset precompute (first 16 CTAs cover all 4096 j's)
    if (blockIdx.x < 16) {
        const int j = blockIdx.x * 256 + threadIdx.x;
        const float xj = x[j];
        int idx = __float2int_rd(fmaf(xj, 16.f, 128.f));
        idx = min(max(idx, 0), GC - 1);
        g_off[j] = (unsigned)idx << 4;
    }

    const float xi = x[i];
    const float u   = fmaf(WA0[2 * hl], xi, bA0[hl]);
    const float v   = WA0[2 * hl + 1];
    const float w2  = WA2[hl];
    const float b1l = bA1[hl];
    float w1l[16];
    #pragma unroll
    for (int k = 0; k < 16; k++) w1l[k] = WA1[hl * 16 + k];

    const bool tv = (fabsf(v) > 1e-30f);
    const float tk = tv ? __fdividef(-u, v) : 3e30f;
    int rank = 0;
    #pragma unroll
    for (int k = 0; k < 16; k++) {
        float o = __shfl_sync(FULLM, tk, (half << 4) | k);
        rank += (o < tk) || (o == tk && k < hl);
    }
    const unsigned tvball = __ballot_sync(FULLM, tv);
    const int nkh = __popc((tvball >> (half << 4)) & 0xffffu);
    if (tv) { sT[warp][half][rank] = tk; sK[warp][half][rank] = hl; }
    __syncwarp();

    const unsigned aball = __ballot_sync(FULLM, (v < 0.f) || (v == 0.f && u > 0.f));
    const unsigned actmask = (aball >> (half << 4)) & 0xffffu;

    float al = b1l, be = 0.f;
    #pragma unroll
    for (int k = 0; k < 16; k++) {
        const float uk = __shfl_sync(FULLM, u, (half << 4) | k);
        const float vk = __shfl_sync(FULLM, v, (half << 4) | k);
        if (actmask & (1u << k)) {
            al = fmaf(w1l[k], uk, al);
            be = fmaf(w1l[k], vk, be);
        }
    }

    const float cbase = fmaf(wA[0], xi, bA2[0]);
    const float dbase = wA[1];

    int onk = __shfl_xor_sync(FULLM, nkh, 16);
    const int maxnk = max(nkh, onk);

    int cnt = 0;
    for (int s0 = 0; s0 <= maxnk; s0++) {
        if (s0 > 0 && s0 <= nkh) {
            const int kst = sK[warp][half][s0 - 1];
            const float uk = __shfl_sync(FULLM, u, (half << 4) | kst);
            const float vk = __shfl_sync(FULLM, v, (half << 4) | kst);
            const float sw = (vk > 0.f) ? w1l[kst] : -w1l[kst];
            al = fmaf(sw, uk, al);
            be = fmaf(sw, vk, be);
        }
        const bool hasI = (s0 <= nkh);
        const float lo = (s0 == 0)   ? -1e30f : sT[warp][half][s0 - 1];
        const float hi = (s0 >= nkh) ?  1e30f : sT[warp][half][s0];
        bool active = hasI && (hi > lo);

        const float z = __fdividef(-al, be);
        bool zv = active && (fabsf(be) > 1e-30f) && (z > lo) && (z < hi);

        const float w2al = w2 * al, w2be = w2 * be;
        bool sgn = zv ? (be < 0.f)
                      : (fmaf(be, 0.5f * lo + 0.5f * hi, al) > 0.f);

        float cur = lo;
        while (__any_sync(FULLM, active)) {
            float zc = (active && zv) ? z : 3e30f;
            float c1 = (active && sgn) ? w2al : 0.f;
            float c2 = (active && sgn) ? w2be : 0.f;
            #pragma unroll
            for (int o = 8; o; o >>= 1) {
                zc = fminf(zc, __shfl_xor_sync(FULLM, zc, o));
                c1 += __shfl_xor_sync(FULLM, c1, o);
                c2 += __shfl_xor_sync(FULLM, c2, o);
            }
            const float b = fminf(zc, hi);
            if (active && hl == 0) {
                sB[warp][half][cnt]  = (cnt == 0) ? -1e38f : cur;
                sCD[warp][half][cnt] = make_float2(cbase + c1, dbase + c2);
            }
            if (active) cnt++;
            const bool cont = active && (b < hi);
            if (zv && z <= b) { sgn = !sgn; zv = false; }
            cur = b;
            active = cont;
        }
    }

    // pad boundaries (cnt <= 33) and fill the global cell table via monotone walks
    for (int s = cnt + hl; s < 66; s += 16) sB[warp][half][s] = 3e38f;
    __syncwarp();
    const float*  bp  = sB[warp][half];
    const float2* cdp = sCD[warp][half];
    int p = 0;                                // monotone per lane (cells hl, hl+16, ...)
    #pragma unroll
    for (int gi = 0; gi < GC / 16; gi++) {
        const int g = gi * 16 + hl;
        const float xc = fmaf((float)g + 0.5f, 1.0f / 16.0f, -8.0f);
        while (bp[p + 1] <= xc) p++;
        g_cd[i * GC + g] = cdp[p];            // coalesced 16x8B per half-warp
    }
}

// ---------------- apply: 4 rows per CTA, fully unrolled, 5 CTAs/SM ----------------
__global__ void __launch_bounds__(256, 5) pwl_apply4(
    const float* __restrict__ x, const float* __restrict__ A,
    const float* __restrict__ Wm0, const float* __restrict__ bm0,
    const float* __restrict__ Wm1, const float* __restrict__ bm1,
    const float* __restrict__ wf,
    float* __restrict__ out)
{
    __shared__ float4 lutA[GC];          // (c0,d0,c1,d1)
    __shared__ float4 lutB[GC];          // (c2,d2,c3,d3)
    __shared__ float  red[4][8];
    const int tid = threadIdx.x;
    const int i0 = blockIdx.x * 4;

    // prelude: straight copy + interleave (no searches)
    {
        const int g = tid;               // 256 threads == GC
        const float2 c0 = g_cd[(i0 + 0) * GC + g];
        const float2 c1 = g_cd[(i0 + 1) * GC + g];
        const float2 c2 = g_cd[(i0 + 2) * GC + g];
        const float2 c3 = g_cd[(i0 + 3) * GC + g];
        lutA[g] = make_float4(c0.x, c0.y, c1.x, c1.y);
        lutB[g] = make_float4(c2.x, c2.y, c3.x, c3.y);
    }
    __syncthreads();

    const float* __restrict__ r0 = A + (size_t)(i0 + 0) * NN;
    const float* __restrict__ r1 = A + (size_t)(i0 + 1) * NN;
    const float* __restrict__ r2 = A + (size_t)(i0 + 2) * NN;
    const float* __restrict__ r3 = A + (size_t)(i0 + 3) * NN;
    const char* lA = reinterpret_cast<const char*>(lutA);
    const char* lB = reinterpret_cast<const char*>(lutB);

    float acc0 = 0.f, acc1 = 0.f, acc2 = 0.f, acc3 = 0.f;
    #pragma unroll
    for (int q = 0; q < 4; q++) {
        const int j = (q * 256 + tid) * 4;
        const uint4  o4 = __ldg(reinterpret_cast<const uint4*>(g_off + j));
        const float4 x4 = __ldg(reinterpret_cast<const float4*>(x + j));
        const float4 a0 = __ldg(reinterpret_cast<const float4*>(r0 + j));
        const float4 a1 = __ldg(reinterpret_cast<const float4*>(r1 + j));
        const float4 a2 = __ldg(reinterpret_cast<const float4*>(r2 + j));
        const float4 a3 = __ldg(reinterpret_cast<const float4*>(r3 + j));
        const float    xa[4] = {x4.x, x4.y, x4.z, x4.w};
        const unsigned oa[4] = {o4.x, o4.y, o4.z, o4.w};
        const float a0a[4] = {a0.x, a0.y, a0.z, a0.w};
        const float a1a[4] = {a1.x, a1.y, a1.z, a1.w};
        const float a2a[4] = {a2.x, a2.y, a2.z, a2.w};
        const float a3a[4] = {a3.x, a3.y, a3.z, a3.w};
        #pragma unroll
        for (int e = 0; e < 4; e++) {
            const float xj = xa[e];
            const float4 cA = *reinterpret_cast<const float4*>(lA + oa[e]);
            const float4 cB = *reinterpret_cast<const float4*>(lB + oa[e]);
            acc0 = fmaf(a0a[e], fmaf(cA.y, xj, cA.x), acc0);
            acc1 = fmaf(a1a[e], fmaf(cA.w, xj, cA.z), acc1);
            acc2 = fmaf(a2a[e], fmaf(cB.y, xj, cB.x), acc2);
            acc3 = fmaf(a3a[e], fmaf(cB.w, xj, cB.z), acc3);
        }
    }

    #pragma unroll
    for (int o = 16; o; o >>= 1) {
        acc0 += __shfl_xor_sync(FULLM, acc0, o);
        acc1 += __shfl_xor_sync(FULLM, acc1, o);
        acc2 += __shfl_xor_sync(FULLM, acc2, o);
        acc3 += __shfl_xor_sync(FULLM, acc3, o);
    }
    if ((tid & 31) == 0) {
        const int w = tid >> 5;
        red[0][w] = acc0; red[1][w] = acc1; red[2][w] = acc2; red[3][w] = acc3;
    }
    __syncthreads();
    if (tid < 4) {
        const int i = i0 + tid;
        float xA = 0.f;
        #pragma unroll
        for (int w = 0; w < 8; w++) xA += red[tid][w];
        const float xi = x[i];
        float xn = fmaf(wf[0], xi, bm1[0]);
        #pragma unroll
        for (int k = 0; k < 16; k++)
            xn = fmaf(Wm1[k], fmaxf(fmaf(Wm0[k], xi, bm0[k]), 0.f), xn);
        out[i] = xn + xA;
    }
}

extern "C" void kernel_launch(void* const* d_in, const int* in_sizes, int n_in,
                              void* d_out, int out_size) {
    // input order: t, x, A, WA0, bA0, WA1, bA1, WA2, bA2, Wm0, bm0, Wm1, bm1, wA, wf
    const float* x   = (const float*)d_in[1];
    const float* A   = (const float*)d_in[2];
    const float* WA0 = (const float*)d_in[3];
    const float* bA0 = (const float*)d_in[4];
    const float* WA1 = (const float*)d_in[5];
    const float* bA1 = (const float*)d_in[6];
    const float* WA2 = (const float*)d_in[7];
    const float* bA2 = (const float*)d_in[8];
    const float* Wm0 = (const float*)d_in[9];
    const float* bm0 = (const float*)d_in[10];
    const float* Wm1 = (const float*)d_in[11];
    const float* bm1 = (const float*)d_in[12];
    const float* wA  = (const float*)d_in[13];
    const float* wf  = (const float*)d_in[14];
    float* out = (float*)d_out;

    build_pwl2<<<NN / 16, 256>>>(x, WA0, bA0, WA1, bA1, WA2, bA2, wA);
    pwl_apply4<<<NN / 4, 256>>>(x, A, Wm0, bm0, Wm1, bm1, wf, out);
}

// round 17
// speedup vs baseline: 1.0110x; 1.0110x over previous
#include <cuda_runtime.h>
#include <math.h>

#define NN 4096
#define GC 256              // LUT cells over [-8, 8), width 1/16
#define FULLM 0xffffffffu

// global scratch (static — no allocs)
__device__ float2   g_cd[NN * GC];   // per-row per-cell (c, d)
__device__ unsigned g_off[NN];       // per-j LUT byte offset (idx << 4)

// ---------------- build: TWO rows per warp; emits g_cd directly ----------------
__global__ void __launch_bounds__(256) build_pwl2(
    const float* __restrict__ x,
    const float* __restrict__ WA0, const float* __restrict__ bA0,
    const float* __restrict__ WA1, const float* __restrict__ bA1,
    const float* __restrict__ WA2, const float* __restrict__ bA2,
    const float* __restrict__ wA)
{
    __shared__ float  sT[8][2][16];
    __shared__ int    sK[8][2][16];
    __shared__ float  sB[8][2][66];      // segment left bounds, padded
    __shared__ float2 sCD[8][2][64];     // segment (c, d)
    const int warp = threadIdx.x >> 5, lane = threadIdx.x & 31;
    const int half = lane >> 4;
    const int hl   = lane & 15;
    const int i = blockIdx.x * 16 + warp * 2 + half;

    // folded offset precompute (first 16 CTAs cover all 4096 j's)
    if (blockIdx.x < 16) {
        const int j = blockIdx.x * 256 + threadIdx.x;
        const float xj = x[j];
        int idx = __float2int_rd(fmaf(xj, 16.f, 128.f));
        idx = min(max(idx, 0), GC - 1);
        g_off[j] = (unsigned)idx << 4;
    }

    const float xi = x[i];
    const float u   = fmaf(WA0[2 * hl], xi, bA0[hl]);
    const float v   = WA0[2 * hl + 1];
    const float w2  = WA2[hl];
    const float b1l = bA1[hl];
    float w1l[16];
    #pragma unroll
    for (int k = 0; k < 16; k++) w1l[k] = WA1[hl * 16 + k];

    const bool tv = (fabsf(v) > 1e-30f);
    const float tk = tv ? __fdividef(-u, v) : 3e30f;
    int rank = 0;
    #pragma unroll
    for (int k = 0; k < 16; k++) {
        float o = __shfl_sync(FULLM, tk, (half << 4) | k);
        rank += (o < tk) || (o == tk && k < hl);
    }
    const unsigned tvball = __ballot_sync(FULLM, tv);
    const int nkh = __popc((tvball >> (half << 4)) & 0xffffu);
    if (tv) { sT[warp][half][rank] = tk; sK[warp][half][rank] = hl; }
    __syncwarp();

    const unsigned aball = __ballot_sync(FULLM, (v < 0.f) || (v == 0.f && u > 0.f));
    const unsigned actmask = (aball >> (half << 4)) & 0xffffu;

    float al = b1l, be = 0.f;
    #pragma unroll
    for (int k = 0; k < 16; k++) {
        const float uk = __shfl_sync(FULLM, u, (half << 4) | k);
        const float vk = __shfl_sync(FULLM, v, (half << 4) | k);
        if (actmask & (1u << k)) {
            al = fmaf(w1l[k], uk, al);
            be = fmaf(w1l[k], vk, be);
        }
    }

    const float cbase = fmaf(wA[0], xi, bA2[0]);
    const float dbase = wA[1];

    int onk = __shfl_xor_sync(FULLM, nkh, 16);
    const int maxnk = max(nkh, onk);

    int cnt = 0;
    for (int s0 = 0; s0 <= maxnk; s0++) {
        if (s0 > 0 && s0 <= nkh) {
            const int kst = sK[warp][half][s0 - 1];
            const float uk = __shfl_sync(FULLM, u, (half << 4) | kst);
            const float vk = __shfl_sync(FULLM, v, (half << 4) | kst);
            const float sw = (vk > 0.f) ? w1l[kst] : -w1l[kst];
            al = fmaf(sw, uk, al);
            be = fmaf(sw, vk, be);
        }
        const bool hasI = (s0 <= nkh);
        const float lo = (s0 == 0)   ? -1e30f : sT[warp][half][s0 - 1];
        const float hi = (s0 >= nkh) ?  1e30f : sT[warp][half][s0];
        bool active = hasI && (hi > lo);

        const float z = __fdividef(-al, be);
        bool zv = active && (fabsf(be) > 1e-30f) && (z > lo) && (z < hi);

        const float w2al = w2 * al, w2be = w2 * be;
        bool sgn = zv ? (be < 0.f)
                      : (fmaf(be, 0.5f * lo + 0.5f * hi, al) > 0.f);

        float cur = lo;
        while (__any_sync(FULLM, active)) {
            float zc = (active && zv) ? z : 3e30f;
            float c1 = (active && sgn) ? w2al : 0.f;
            float c2 = (active && sgn) ? w2be : 0.f;
            #pragma unroll
            for (int o = 8; o; o >>= 1) {
                zc = fminf(zc, __shfl_xor_sync(FULLM, zc, o));
                c1 += __shfl_xor_sync(FULLM, c1, o);
                c2 += __shfl_xor_sync(FULLM, c2, o);
            }
            const float b = fminf(zc, hi);
            if (active && hl == 0) {
                sB[warp][half][cnt]  = (cnt == 0) ? -1e38f : cur;
                sCD[warp][half][cnt] = make_float2(cbase + c1, dbase + c2);
            }
            if (active) cnt++;
            const bool cont = active && (b < hi);
            if (zv && z <= b) { sgn = !sgn; zv = false; }
            cur = b;
            active = cont;
        }
    }

    // pad boundaries (cnt <= 33) and fill the global cell table via monotone walks
    for (int s = cnt + hl; s < 66; s += 16) sB[warp][half][s] = 3e38f;
    __syncwarp();
    const float*  bp  = sB[warp][half];
    const float2* cdp = sCD[warp][half];
    int p = 0;                                // monotone per lane (cells hl, hl+16, ...)
    #pragma unroll
    for (int gi = 0; gi < GC / 16; gi++) {
        const int g = gi * 16 + hl;
        const float xc = fmaf((float)g + 0.5f, 1.0f / 16.0f, -8.0f);
        while (bp[p + 1] <= xc) p++;
        g_cd[i * GC + g] = cdp[p];            // coalesced 16x8B per half-warp
    }
}

// ---------------- apply: 4 rows per CTA, fully unrolled (R13-exact) ----------------
__global__ void __launch_bounds__(256) pwl_apply4(
    const float* __restrict__ x, const float* __restrict__ A,
    const float* __restrict__ Wm0, const float* __restrict__ bm0,
    const float* __restrict__ Wm1, const float* __restrict__ bm1,
    const float* __restrict__ wf,
    float* __restrict__ out)
{
    __shared__ float4 lutA[GC];          // (c0,d0,c1,d1)
    __shared__ float4 lutB[GC];          // (c2,d2,c3,d3)
    __shared__ float  red[4][8];
    const int tid = threadIdx.x;
    const int i0 = blockIdx.x * 4;

    // prelude: straight copy + interleave (no searches)
    {
        const int g = tid;               // 256 threads == GC
        const float2 c0 = g_cd[(i0 + 0) * GC + g];
        const float2 c1 = g_cd[(i0 + 1) * GC + g];
        const float2 c2 = g_cd[(i0 + 2) * GC + g];
        const float2 c3 = g_cd[(i0 + 3) * GC + g];
        lutA[g] = make_float4(c0.x, c0.y, c1.x, c1.y);
        lutB[g] = make_float4(c2.x, c2.y, c3.x, c3.y);
    }
    __syncthreads();

    const float* __restrict__ r0 = A + (size_t)(i0 + 0) * NN;
    const float* __restrict__ r1 = A + (size_t)(i0 + 1) * NN;
    const float* __restrict__ r2 = A + (size_t)(i0 + 2) * NN;
    const float* __restrict__ r3 = A + (size_t)(i0 + 3) * NN;
    const char* lA = reinterpret_cast<const char*>(lutA);
    const char* lB = reinterpret_cast<const char*>(lutB);

    float acc0 = 0.f, acc1 = 0.f, acc2 = 0.f, acc3 = 0.f;
    #pragma unroll
    for (int q = 0; q < 4; q++) {
        const int j = (q * 256 + tid) * 4;
        const uint4  o4 = __ldg(reinterpret_cast<const uint4*>(g_off + j));
        const float4 x4 = __ldg(reinterpret_cast<const float4*>(x + j));
        const float4 a0 = __ldg(reinterpret_cast<const float4*>(r0 + j));
        const float4 a1 = __ldg(reinterpret_cast<const float4*>(r1 + j));
        const float4 a2 = __ldg(reinterpret_cast<const float4*>(r2 + j));
        const float4 a3 = __ldg(reinterpret_cast<const float4*>(r3 + j));
        const float    xa[4] = {x4.x, x4.y, x4.z, x4.w};
        const unsigned oa[4] = {o4.x, o4.y, o4.z, o4.w};
        const float a0a[4] = {a0.x, a0.y, a0.z, a0.w};
        const float a1a[4] = {a1.x, a1.y, a1.z, a1.w};
        const float a2a[4] = {a2.x, a2.y, a2.z, a2.w};
        const float a3a[4] = {a3.x, a3.y, a3.z, a3.w};
        #pragma unroll
        for (int e = 0; e < 4; e++) {
            const float xj = xa[e];
            const float4 cA = *reinterpret_cast<const float4*>(lA + oa[e]);
            const float4 cB = *reinterpret_cast<const float4*>(lB + oa[e]);
            acc0 = fmaf(a0a[e], fmaf(cA.y, xj, cA.x), acc0);
            acc1 = fmaf(a1a[e], fmaf(cA.w, xj, cA.z), acc1);
            acc2 = fmaf(a2a[e], fmaf(cB.y, xj, cB.x), acc2);
            acc3 = fmaf(a3a[e], fmaf(cB.w, xj, cB.z), acc3);
        }
    }

    #pragma unroll
    for (int o = 16; o; o >>= 1) {
        acc0 += __shfl_xor_sync(FULLM, acc0, o);
        acc1 += __shfl_xor_sync(FULLM, acc1, o);
        acc2 += __shfl_xor_sync(FULLM, acc2, o);
        acc3 += __shfl_xor_sync(FULLM, acc3, o);
    }
    if ((tid & 31) == 0) {
        const int w = tid >> 5;
        red[0][w] = acc0; red[1][w] = acc1; red[2][w] = acc2; red[3][w] = acc3;
    }
    __syncthreads();
    if (tid < 4) {
        const int i = i0 + tid;
        float xA = 0.f;
        #pragma unroll
        for (int w = 0; w < 8; w++) xA += red[tid][w];
        const float xi = x[i];
        float xn = fmaf(wf[0], xi, bm1[0]);
        #pragma unroll
        for (int k = 0; k < 16; k++)
            xn = fmaf(Wm1[k], fmaxf(fmaf(Wm0[k], xi, bm0[k]), 0.f), xn);
        out[i] = xn + xA;
    }
}

extern "C" void kernel_launch(void* const* d_in, const int* in_sizes, int n_in,
                              void* d_out, int out_size) {
    // input order: t, x, A, WA0, bA0, WA1, bA1, WA2, bA2, Wm0, bm0, Wm1, bm1, wA, wf
    const float* x   = (const float*)d_in[1];
    const float* A   = (const float*)d_in[2];
    const float* WA0 = (const float*)d_in[3];
    const float* bA0 = (const float*)d_in[4];
    const float* WA1 = (const float*)d_in[5];
    const float* bA1 = (const float*)d_in[6];
    const float* WA2 = (const float*)d_in[7];
    const float* bA2 = (const float*)d_in[8];
    const float* Wm0 = (const float*)d_in[9];
    const float* bm0 = (const float*)d_in[10];
    const float* Wm1 = (const float*)d_in[11];
    const float* bm1 = (const float*)d_in[12];
    const float* wA  = (const float*)d_in[13];
    const float* wf  = (const float*)d_in[14];
    float* out = (float*)d_out;

    build_pwl2<<<NN / 16, 256>>>(x, WA0, bA0, WA1, bA1, WA2, bA2, wA);
    pwl_apply4<<<NN / 4, 256>>>(x, A, Wm0, bm0, Wm1, bm1, wf, out);
}